// round 16
// baseline (speedup 1.0000x reference)
#include <cuda_runtime.h>
#include <cuda_bf16.h>
#include <cstdint>

// CTC forward negative log-likelihood (keras ctc_batch_cost semantics).
// B=128, T=1024, V=512, L=128, S=2L+1=257, blank=V-1.
//
// Round-16 design ("composed 2-step + shuffle probs + balanced 8 warps"):
//  - 1 CTA/batch (grid=128), 256 threads (8 warps = exactly 2/SMSP).
//    Thread s=tid owns state s; tid 255 additionally owns state 256.
//  - Composed 2-step update (ONE barrier per 2 time steps):
//      alpha_{t+2}[s] = m + lg2( (sum_j W_j * 2^(alpha_t[s-j]-m)) * q_s )
//    LINEAR path weights (FMA only):
//      W0 = p_s ; W1 = p_s + p_m1 ; W2 = cs_s ? (W1 + p_m2) : p_m1
//      W3 = (cs_m1 ? p_m1 : 0) + (cs_s ? p_m2 : 0) ; W4 = (cs_s&&cs_m2)?p_m2:0
//  - SHUFFLE PROB DELIVERY: thread s scatter-loads only P0 = row[class(s)]
//    and Qs = row'[class(s)]. P1 = thread (s-1)'s P0 via __shfl_up(.,1),
//    P2 = thread (s-2)'s P0 via __shfl_up(.,2); lanes 0/1 fix up with
//    predicated direct LDS. Halves scattered smem wavefronts.
//  - State 256 (even/blank) on tid 255: weights need p(blank)=own P1,
//    p(lab127)=own P0; alphas A[253..256] already loaded/carried. +1 LDS (Qb).
//  - cp.async D=16 row ring (32KB), producers tid<128, 2 rows/commit group,
//    wait_group<4>: at iteration t all rows <= t+7 complete -> pre-barrier
//    prefetch of rows t+2,t+3 is race-free and never blocks (R14 invariant).

#define NEGV (-1e30f)
#define EPSV (1e-7f)
#define LN2F (0.6931471805599453f)

constexpr int Bc = 128;
constexpr int Tc = 1024;
constexpr int Vc = 512;
constexpr int Lc = 128;
constexpr int Sc = 257;     // 2L+1
constexpr int D  = 16;      // ring stages (32KB)
constexpr int NT = 256;     // 8 warps

__device__ __forceinline__ float ex2f(float x) {
    float r; asm("ex2.approx.f32 %0, %1;" : "=f"(r) : "f"(x)); return r;
}
__device__ __forceinline__ float lg2f(float x) {
    float r; asm("lg2.approx.f32 %0, %1;" : "=f"(r) : "f"(x)); return r;
}
__device__ __forceinline__ void cp_async16(uint32_t saddr, const void* gptr) {
    asm volatile("cp.async.cg.shared.global [%0], [%1], 16;" :: "r"(saddr), "l"(gptr));
}
__device__ __forceinline__ void cp_commit() {
    asm volatile("cp.async.commit_group;");
}
template<int N>
__device__ __forceinline__ void cp_wait() {
    asm volatile("cp.async.wait_group %0;" :: "n"(N));
}

__global__ __launch_bounds__(NT, 1)
void ctc_forward_kernel(const int*   __restrict__ labels,     // [B, L]
                        const int*   __restrict__ lab_len,    // [B, 1]
                        const float* __restrict__ Y,          // [B, T, V]
                        const int*   __restrict__ in_len,     // [B, 1]
                        float*       __restrict__ out)        // [B, 1]
{
    __shared__ __align__(16) float rows[D][Vc];   // staged probability rows (32KB)
    __shared__ float As[2][Sc + 8];               // alpha: 4 front-pad + 257 + tail
    __shared__ int   lab_sh[Lc];

    const int b    = blockIdx.x;
    const int tid  = threadIdx.x;
    const int lane = tid & 31;

    if (tid < Lc) lab_sh[tid] = labels[b * Lc + tid];
    const int len = in_len[b];

    const int  s     = tid;
    const bool xtra  = (tid == NT - 1);           // also owns state 256

    if (tid < 4) { As[0][tid] = NEGV; As[1][tid] = NEGV; }
    As[0][4 + s] = (s == 0) ? 0.0f : NEGV;        // log2 domain
    if (xtra) As[0][4 + 256] = NEGV;

    const float* __restrict__ Yb = Y + (size_t)b * Tc * Vc;
    const bool producer = (tid < 128);            // cp.async warps 0-3
    const uint32_t rows_sb = (uint32_t)__cvta_generic_to_shared(&rows[0][0]);

    // ---- prologue: stage rows 0..D-1 (2 rows per commit group, 8 groups) ----
    if (producer) {
        #pragma unroll
        for (int g = 0; g < D / 2; g++) {
            #pragma unroll
            for (int r = 0; r < 2; r++) {
                const int j  = 2 * g + r;
                const int tr = (j < len) ? j : (len > 0 ? len - 1 : 0);
                cp_async16(rows_sb + (uint32_t)j * 2048u + (uint32_t)tid * 16u,
                           Yb + (size_t)tr * Vc + tid * 4);
            }
            cp_commit();
        }
        cp_wait<4>();                 // groups 0..3 complete -> rows 0..7
    }
    __syncthreads();                  // labels, alpha0, rows 0..7 visible

    // ---- per-thread constants ----
    const int  blank = Vc - 1;
    const bool sOdd  = (s & 1) != 0;
    int  cls_s  = blank, cls_m1 = blank, cls_m2 = blank;
    bool cs_s = false, cs_m1 = false, cs_m2 = false;
    if (sOdd) {
        cls_s  = lab_sh[(s - 1) >> 1];
        cls_m2 = (s >= 3) ? lab_sh[(s - 3) >> 1] : blank;
        cs_s   = (s >= 3) && (cls_s != cls_m2) && (cls_s != blank);
        cs_m2  = (s >= 5) && (lab_sh[(s - 3) >> 1] != lab_sh[(s - 5) >> 1])
                          && (cls_m2 != blank);
    } else {
        cls_m1 = (s >= 2) ? lab_sh[(s - 2) >> 1] : blank;
        cs_m1  = (s >= 4) && (lab_sh[(s - 2) >> 1] != lab_sh[(s - 4) >> 1])
                          && (cls_m1 != blank);
    }
    const bool pm3 = cs_m1 || cs_s;       // W3 > 0 ?
    const bool pm4 = cs_s && cs_m2;       // W4 > 0 ?

    // ---- initial prefetch for iteration 0 (rows 0,1 complete) ----
    float P0 = rows[0][cls_s]  + EPSV;
    float P1 = rows[0][cls_m1] + EPSV;
    float P2 = rows[0][cls_m2] + EPSV;
    float Qs = rows[1][cls_s]  + EPSV;
    float Qb = 0.0f;
    if (xtra) Qb = rows[1][blank] + EPSV;

    float aPrev = (s == 0) ? 0.0f : NEGV;     // alpha_t[s] in register
    float a256  = NEGV;                       // alpha_t[256] (tid 255 only)

    // ---- main recursion: 2 composed steps per barrier ----
    int rd = 0;
    int t  = 0;
    for (; t + 1 < len; t += 2) {
        // ---- compute alpha_{t+2}[s] ----
        {
            const float W0 = P0;
            const float W1 = P0 + P1;
            const float W2 = cs_s ? (W1 + P2) : P1;
            const float W3 = (cs_m1 ? P1 : 0.0f) + (cs_s ? P2 : 0.0f);
            const float W4 = pm4 ? P2 : 0.0f;

            const float* __restrict__ A = &As[rd][4];
            const float A0 = aPrev;
            const float A1 = A[s - 1];
            const float A2 = A[s - 2];
            const float A3r = A[s - 3];
            const float A3 = pm3 ? A3r : NEGV;
            const float A4 = pm4 ? A[s - 4] : NEGV;

            const float m = fmaxf(fmaxf(fmaxf(A0, A1), fmaxf(A2, A3)), A4);
            const float x0 = ex2f(A0 - m);
            const float x1 = ex2f(A1 - m);
            const float x2 = ex2f(A2 - m);
            const float x3 = ex2f(A3 - m);
            const float x4 = ex2f(A4 - m);
            const float sum = (W0 * x0 + W1 * x1) + (W2 * x2 + (W3 * x3 + W4 * x4));
            const float n = m + lg2f(sum * Qs);
            As[rd ^ 1][4 + s] = n;

            // ---- state 256 (tid 255 only; even/blank, cs(256)=false) ----
            // classes: p(blank)=P1 (s=255 odd -> P1 is blank), p(lab127)=P0.
            // alphas: A[256]=a256, A[255]=A0, A[254]=A1, A[253]=A2.
            if (xtra) {
                const float V0 = P1;                   // W0 = p(blank)
                const float V1 = P1 + P0;              // W1
                const float V2 = P0;                   // W2 (no skip into 256)
                const float V3 = cs_s ? P0 : 0.0f;     // W3 (cs(255) = cs_s)
                const float B0 = a256;
                const float B1 = A0;
                const float B2 = A1;
                const float B3 = cs_s ? A2 : NEGV;
                const float mx = fmaxf(fmaxf(B0, B1), fmaxf(B2, B3));
                const float y0 = ex2f(B0 - mx);
                const float y1 = ex2f(B1 - mx);
                const float y2 = ex2f(B2 - mx);
                const float y3 = ex2f(B3 - mx);
                const float sx = (V0 * y0 + V1 * y1) + (V2 * y2 + V3 * y3);
                const float n256 = mx + lg2f(sx * Qb);
                As[rd ^ 1][4 + 256] = n256;
                a256 = n256;
            }
            aPrev = n;
        }

        // ---- prefetch for iteration t+2 (rows t+2,t+3): race-free under
        //      wait<4>/D=16 (rows <= t+7 complete & visible). Only P0/Qs are
        //      scattered; P1/P2 delivered by shuffle from neighbor threads.
        if (t + 3 < len) {
            const float* __restrict__ r2 = rows[(t + 2) & (D - 1)];
            const float* __restrict__ r3 = rows[(t + 3) & (D - 1)];
            const float p0n = r2[cls_s] + EPSV;
            const float qsn = r3[cls_s] + EPSV;
            float p1n = __shfl_up_sync(0xffffffffu, p0n, 1);
            float p2n = __shfl_up_sync(0xffffffffu, p0n, 2);
            if (lane == 0) p1n = r2[cls_m1] + EPSV;
            if (lane <  2) p2n = r2[cls_m2] + EPSV;
            if (xtra)      Qb  = r3[blank]  + EPSV;
            P0 = p0n; P1 = p1n; P2 = p2n; Qs = qsn;
        } else if (t + 2 < len) {
            P0 = rows[(t + 2) & (D - 1)][cls_s] + EPSV;   // odd tail: p_s
            float p1n = __shfl_up_sync(0xffffffffu, P0, 1);
            if (lane == 0) p1n = rows[(t + 2) & (D - 1)][cls_m1] + EPSV;
            P1 = p1n;                                      // blank for tail-256
        }

        if (producer) cp_wait<4>();   // all but newest 4 groups complete
        __syncthreads();              // publish alpha_{t+2}; rows visible; slots retired
        if (producer && (t + D) < len) {
            #pragma unroll
            for (int r = 0; r < 2; r++) {
                const int j  = t + D + r;
                const int tr = (j < len) ? j : (len - 1);
                cp_async16(rows_sb + (uint32_t)(j & (D - 1)) * 2048u + (uint32_t)tid * 16u,
                           Yb + (size_t)tr * Vc + tid * 4);
            }
            cp_commit();
        }
        rd ^= 1;
    }

    // ---- odd tail: one single step (len odd) ----
    if (t < len) {
        const float* __restrict__ A = &As[rd][4];
        const float A0 = aPrev;
        const float A1 = A[s - 1];
        const float A2 = cs_s ? A[s - 2] : NEGV;
        const float m  = fmaxf(fmaxf(A0, A1), A2);
        const float sum = ex2f(A0 - m) + ex2f(A1 - m) + ex2f(A2 - m);
        As[rd ^ 1][4 + s] = m + lg2f(sum * P0);   // P0 = p_s at row t
        if (xtra) {                               // state 256: (a256 + a255)*blank
            const float mx = fmaxf(a256, A0);
            const float sx = ex2f(a256 - mx) + ex2f(A0 - mx);
            As[rd ^ 1][4 + 256] = mx + lg2f(sx * P1);   // P1 = blank at row t
        }
        __syncthreads();
        rd ^= 1;
    }

    // ---- final: loss = -ln2 * logaddexp2(alpha[2*lab], alpha[2*lab-1]) ----
    if (tid == 0) {
        const int   ll = lab_len[b];
        const float aL = As[rd][4 + 2 * ll];
        const float aP = As[rd][4 + 2 * ll - 1];
        const float mm = fmaxf(aL, aP);
        const float ql = fminf(aL, aP);
        out[b] = -LN2F * (mm + lg2f(1.0f + ex2f(ql - mm)));
    }
}

extern "C" void kernel_launch(void* const* d_in, const int* in_sizes, int n_in,
                              void* d_out, int out_size) {
    const int*   labels  = (const int*)d_in[0];   // true_labels [B, L]
    const int*   lab_len = (const int*)d_in[1];   // true_lengths [B, 1]
    const float* Y       = (const float*)d_in[2]; // predicted_labels [B, T, V]
    const int*   in_len  = (const int*)d_in[3];   // predicted_lengths [B, 1]
    float*       out     = (float*)d_out;         // [B, 1]

    ctc_forward_kernel<<<Bc, NT>>>(labels, lab_len, Y, in_len, out);
}

// round 17
// speedup vs baseline: 1.6507x; 1.6507x over previous
#include <cuda_runtime.h>
#include <cuda_bf16.h>
#include <cstdint>

// CTC forward negative log-likelihood (keras ctc_batch_cost semantics).
// B=128, T=1024, V=512, L=128, S=2L+1=257, blank=V-1.
//
// Round-17 design ("R14 + balanced copies, pre-barrier issue, reg A0"):
//  - 1 CTA/batch (grid=128), 288 threads (9 warps). Thread s=tid owns state s
//    (conflict-free alpha LDS/STS), 4-entry NEGV front pad, ONE __syncthreads
//    per 2 time steps. cp.async D=16 row ring (32KB).
//  - Composed 2-step update (5-term weighted logsumexp, LINEAR path weights):
//      W0 = p_s ; W1 = p_s + p_m1 ; W2 = cs_s ? (W1 + p_m2) : p_m1
//      W3 = (cs_m1 ? p_m1 : 0) + (cs_s ? p_m2 : 0) ; W4 = (cs_s&&cs_m2)?p_m2:0
//    Exactly equivalent to two chained logaddexp2 steps.
//  - NEW vs R14:
//    (a) Copy work spread: 256 threads x ONE cp_async16 per iteration
//        (2 rows = 4096B), halving producer-warp LSU load -> less skew.
//    (b) cp.async issued PRE-barrier: slots t,t+1 were last read in iter
//        t-2's prefetch (a barrier ago) -> WAR-safe; DMA starts earlier and
//        the post-barrier producer tail disappears. wait_group<5>: with the
//        newest group committed this iteration, <=5 pending means groups
//        issued <= iter t-10 are done -> rows <= t+7 complete at iter-t end;
//        the prefetch at iter t+2 touches rows t+4,t+5 (margin 2). Race-free.
//    (c) A0 = alpha_t[s] carried in register aPrev (one fewer LDS on chain).

#define NEGV (-1e30f)
#define EPSV (1e-7f)
#define LN2F (0.6931471805599453f)

constexpr int Bc = 128;
constexpr int Tc = 1024;
constexpr int Vc = 512;
constexpr int Lc = 128;
constexpr int Sc = 257;     // 2L+1
constexpr int D  = 16;      // ring stages (32KB)
constexpr int NT = 288;     // 9 warps

__device__ __forceinline__ float ex2f(float x) {
    float r; asm("ex2.approx.f32 %0, %1;" : "=f"(r) : "f"(x)); return r;
}
__device__ __forceinline__ float lg2f(float x) {
    float r; asm("lg2.approx.f32 %0, %1;" : "=f"(r) : "f"(x)); return r;
}
__device__ __forceinline__ void cp_async16(uint32_t saddr, const void* gptr) {
    asm volatile("cp.async.cg.shared.global [%0], [%1], 16;" :: "r"(saddr), "l"(gptr));
}
__device__ __forceinline__ void cp_commit() {
    asm volatile("cp.async.commit_group;");
}
template<int N>
__device__ __forceinline__ void cp_wait() {
    asm volatile("cp.async.wait_group %0;" :: "n"(N));
}

__global__ __launch_bounds__(NT, 1)
void ctc_forward_kernel(const int*   __restrict__ labels,     // [B, L]
                        const int*   __restrict__ lab_len,    // [B, 1]
                        const float* __restrict__ Y,          // [B, T, V]
                        const int*   __restrict__ in_len,     // [B, 1]
                        float*       __restrict__ out)        // [B, 1]
{
    __shared__ __align__(16) float rows[D][Vc];   // staged probability rows (32KB)
    __shared__ float As[2][Sc + 8];               // alpha: 4 front-pad + 257 + tail
    __shared__ int   lab_sh[Lc];

    const int b   = blockIdx.x;
    const int tid = threadIdx.x;

    if (tid < Lc) lab_sh[tid] = labels[b * Lc + tid];
    const int len = in_len[b];

    const bool active = (tid <= 256);
    const int  s      = tid;

    if (tid < 4) { As[0][tid] = NEGV; As[1][tid] = NEGV; }
    if (active) As[0][4 + s] = (s == 0) ? 0.0f : NEGV;    // log2 domain

    const float* __restrict__ Yb = Y + (size_t)b * Tc * Vc;
    const bool producer = (tid < 256);            // 256 threads x 16B = 2 rows
    const int  prow = tid >> 7;                   // 0 or 1: which row of the pair
    const int  pcol = (tid & 127) * 4;            // float offset within row
    const uint32_t rows_sb = (uint32_t)__cvta_generic_to_shared(&rows[0][0]);

    // ---- prologue: stage rows 0..D-1 (2 rows per commit group, 8 groups) ----
    if (producer) {
        #pragma unroll
        for (int g = 0; g < D / 2; g++) {
            const int j  = 2 * g + prow;
            const int tr = (j < len) ? j : (len > 0 ? len - 1 : 0);
            cp_async16(rows_sb + (uint32_t)j * 2048u + (uint32_t)(tid & 127) * 16u,
                       Yb + (size_t)tr * Vc + pcol);
            cp_commit();
        }
        cp_wait<4>();                 // groups 0..3 complete -> rows 0..7
    }
    __syncthreads();                  // labels, alpha0, rows 0..7 visible

    // ---- per-thread constants ----
    const int  blank = Vc - 1;
    const bool sOdd  = (s & 1) != 0;
    int  cls_s  = blank, cls_m1 = blank, cls_m2 = blank;
    bool cs_s = false, cs_m1 = false, cs_m2 = false;
    if (active) {
        if (sOdd) {
            cls_s  = lab_sh[(s - 1) >> 1];
            cls_m2 = (s >= 3) ? lab_sh[(s - 3) >> 1] : blank;
            cs_s   = (s >= 3) && (cls_s != cls_m2) && (cls_s != blank);
            cs_m2  = (s >= 5) && (lab_sh[(s - 3) >> 1] != lab_sh[(s - 5) >> 1])
                              && (cls_m2 != blank);
        } else {
            cls_m1 = (s >= 2) ? lab_sh[(s - 2) >> 1] : blank;
            cs_m1  = (s >= 4) && (lab_sh[(s - 2) >> 1] != lab_sh[(s - 4) >> 1])
                              && (cls_m1 != blank);
        }
    }
    const bool pm3 = cs_m1 || cs_s;       // W3 > 0 ?
    const bool pm4 = cs_s && cs_m2;       // W4 > 0 ?

    // ---- prefetch p/q for iteration t=0 (rows 0,1 complete) ----
    float P0 = EPSV, P1 = EPSV, P2 = EPSV, Qs = EPSV;
    if (active) {
        P0 = rows[0][cls_s]  + EPSV;
        P1 = rows[0][cls_m1] + EPSV;
        P2 = rows[0][cls_m2] + EPSV;
        Qs = rows[1][cls_s]  + EPSV;
    }
    float aPrev = (s == 0) ? 0.0f : NEGV;     // alpha_t[s] carried in register

    // ---- main recursion: 2 composed steps per barrier ----
    int rd = 0;
    int t  = 0;
    for (; t + 1 < len; t += 2) {
        if (active) {
            // linear path weights (FMA/ALU only)
            const float W0 = P0;
            const float W1 = P0 + P1;
            const float W2 = cs_s ? (W1 + P2) : P1;
            const float W3 = (cs_m1 ? P1 : 0.0f) + (cs_s ? P2 : 0.0f);
            const float W4 = pm4 ? P2 : 0.0f;

            const float* __restrict__ A = &As[rd][4];   // A[i] = alpha_t[i]
            const float A0 = aPrev;                     // own alpha (register)
            const float A1 = A[s - 1];
            const float A2 = A[s - 2];
            const float A3 = pm3 ? A[s - 3] : NEGV;     // mask zero-weight terms
            const float A4 = pm4 ? A[s - 4] : NEGV;

            const float m = fmaxf(fmaxf(fmaxf(A0, A1), fmaxf(A2, A3)), A4);
            const float x0 = ex2f(A0 - m);
            const float x1 = ex2f(A1 - m);
            const float x2 = ex2f(A2 - m);
            const float x3 = ex2f(A3 - m);
            const float x4 = ex2f(A4 - m);
            const float sum = (W0 * x0 + W1 * x1) + (W2 * x2 + (W3 * x3 + W4 * x4));
            const float n = m + lg2f(sum * Qs);
            As[rd ^ 1][4 + s] = n;
            aPrev = n;

            // Race-free prefetch for iteration t+2: rows t+2,t+3 complete
            // before iter t's opening barrier (wait<5> invariant: at end of
            // iter t-2, rows <= t+5 complete) and visible via that barrier.
            if (t + 3 < len) {
                const float* __restrict__ r0n = rows[(t + 2) & (D - 1)];
                const float* __restrict__ r1n = rows[(t + 3) & (D - 1)];
                P0 = r0n[cls_s]  + EPSV;
                P1 = r0n[cls_m1] + EPSV;
                P2 = r0n[cls_m2] + EPSV;
                Qs = r1n[cls_s]  + EPSV;
            } else if (t + 2 < len) {
                P0 = rows[(t + 2) & (D - 1)][cls_s] + EPSV;   // odd tail
            }
        }

        // PRE-barrier copy issue (WAR-safe: slots t,t+1 last read in iter
        // t-2's prefetch, separated from this write by iter t-2's barrier).
        if (producer && (t + D) < len) {
            const int j  = t + D + prow;
            const int tr = (j < len) ? j : (len - 1);
            cp_async16(rows_sb + (uint32_t)(j & (D - 1)) * 2048u
                               + (uint32_t)(tid & 127) * 16u,
                       Yb + (size_t)tr * Vc + pcol);
            cp_commit();
        }
        if (producer) cp_wait<5>();   // all but newest 5 groups complete
        __syncthreads();              // publish alpha_{t+2}; rows visible; slots retired
        rd ^= 1;
    }

    // ---- odd tail: one single step (len odd) ----
    if (t < len) {
        if (active) {
            const float* __restrict__ A = &As[rd][4];
            const float A0 = aPrev;
            const float A1 = A[s - 1];
            const float A2 = cs_s ? A[s - 2] : NEGV;
            const float m  = fmaxf(fmaxf(A0, A1), A2);
            const float sum = ex2f(A0 - m) + ex2f(A1 - m) + ex2f(A2 - m);
            As[rd ^ 1][4 + s] = m + lg2f(sum * P0);   // P0 = p_s at row t
        }
        __syncthreads();
        rd ^= 1;
    }

    // ---- final: loss = -ln2 * logaddexp2(alpha[2*lab], alpha[2*lab-1]) ----
    if (tid == 0) {
        const int   ll = lab_len[b];
        const float aL = As[rd][4 + 2 * ll];
        const float aP = As[rd][4 + 2 * ll - 1];
        const float mm = fmaxf(aL, aP);
        const float ql = fminf(aL, aP);
        out[b] = -LN2F * (mm + lg2f(1.0f + ex2f(ql - mm)));
    }
}

extern "C" void kernel_launch(void* const* d_in, const int* in_sizes, int n_in,
                              void* d_out, int out_size) {
    const int*   labels  = (const int*)d_in[0];   // true_labels [B, L]
    const int*   lab_len = (const int*)d_in[1];   // true_lengths [B, 1]
    const float* Y       = (const float*)d_in[2]; // predicted_labels [B, T, V]
    const int*   in_len  = (const int*)d_in[3];   // predicted_lengths [B, 1]
    float*       out     = (float*)d_out;         // [B, 1]

    ctc_forward_kernel<<<Bc, NT>>>(labels, lab_len, Y, in_len, out);
}